// round 16
// baseline (speedup 1.0000x reference)
#include <cuda_runtime.h>
#include <cuda_bf16.h>
#include <cuda_fp16.h>
#include <cstdint>

#define EPSF 1e-5f
#define HW   16384
#define CHW  2097152

// ---------------- scratch (static device memory) ----------------
__device__ float g_bcf[5*128];                          // composed biases
__device__ __align__(16) unsigned short g_wsh[5*2*128*64];   // fp16 [which][pn][o][ci64]
__device__ __align__(16) unsigned short g_tih[3ull*8*CHW];   // fp16 inputs T: [inp][b][h][w][c]
__device__ unsigned short g_wh[9*6*384*64];             // conv3x3 W fp16: [tap][chunk][o][ci]
__device__ unsigned short g_bhi[8ull*130*130*384];      // conv3x3 in fp16: [b][hp][wp][ci]

// ---------------- helpers ----------------
__device__ __forceinline__ uint32_t smem_u32(const void* p){
    uint32_t a; asm("{ .reg .u64 t; cvta.to.shared.u64 t, %1; cvt.u32.u64 %0, t; }"
                    : "=r"(a) : "l"(p)); return a;
}
#define SWZ(x) ((x) ^ (((x)>>3)&0x70))
#define CP16(dst, src) asm volatile("cp.async.cg.shared.global [%0], [%1], 16;" \
    :: "r"((uint32_t)(dst)), "l"((const void*)(src)) : "memory")
#define CP_COMMIT() asm volatile("cp.async.commit_group;" ::: "memory")
#define CP_WAIT0()  asm volatile("cp.async.wait_group 0;" ::: "memory")
#define CP_WAIT1()  asm volatile("cp.async.wait_group 1;" ::: "memory")
#define LDSM4(r0,r1,r2,r3,a) asm volatile( \
    "ldmatrix.sync.aligned.m8n8.x4.shared.b16 {%0,%1,%2,%3}, [%4];" \
    : "=r"(r0),"=r"(r1),"=r"(r2),"=r"(r3) : "r"(a))
#define MMAF16(c,a,b) asm volatile( \
    "mma.sync.aligned.m16n8k16.row.col.f32.f16.f16.f32 " \
    "{%0,%1,%2,%3},{%4,%5,%6,%7},{%8,%9},{%0,%1,%2,%3};" \
    : "+f"((c)[0]),"+f"((c)[1]),"+f"((c)[2]),"+f"((c)[3]) \
    : "r"((a)[0]),"r"((a)[1]),"r"((a)[2]),"r"((a)[3]), "r"((b)[0]),"r"((b)[1]))

__device__ __forceinline__ unsigned pack_f16(float v0, float v1){
    unsigned hp; asm("cvt.rn.f16x2.f32 %0, %1, %2;" : "=r"(hp) : "f"(v1), "f"(v0));
    return hp;
}

// 128x128x64 GEMM chunk, single-pass fp16, ks-pipelined fragment loads.
__device__ __forceinline__ void gemm64f(uint32_t sb, uint32_t a0, uint32_t b0,
                                        int l, int mw, int nw, float acc[4][4][4])
{
    uint32_t ah[2][4][4], bh[2][4][2];
    auto loadf = [&](int ks, int buf){
        const uint32_t abyte = (uint32_t)(ks*32) + ((l>>4)<<4);
#pragma unroll
        for (int f = 0; f < 4; f++){
            int row = mw*64 + f*16 + (l & 15);
            uint32_t off = SWZ((uint32_t)(row*128) + abyte);
            LDSM4(ah[buf][f][0],ah[buf][f][1],ah[buf][f][2],ah[buf][f][3], sb + a0 + off);
        }
        const uint32_t bbyte = (uint32_t)(ks*32) + (((l>>3)&1)<<4);
#pragma unroll
        for (int g2 = 0; g2 < 2; g2++){
            int rowb = nw*32 + g2*16 + (l & 7) + ((l>>4)<<3);
            uint32_t off = SWZ((uint32_t)(rowb*128) + bbyte);
            uint32_t t0,t1,t2,t3;
            LDSM4(t0,t1,t2,t3, sb + b0 + off);
            bh[buf][g2*2][0]=t0; bh[buf][g2*2][1]=t1;
            bh[buf][g2*2+1][0]=t2; bh[buf][g2*2+1][1]=t3;
        }
    };
    loadf(0, 0);
#pragma unroll
    for (int ks = 0; ks < 4; ks++){
        const int cur = ks & 1;
        if (ks < 3) loadf(ks+1, cur^1);
#pragma unroll
        for (int f = 0; f < 4; f++)
#pragma unroll
            for (int g = 0; g < 4; g++)
                MMAF16(acc[f][g], ah[cur][f], bh[cur][g]);
    }
}

__device__ __forceinline__ void block_reduce_2(float& s, float& q, float* red)
{
#pragma unroll
    for (int off=16; off>0; off>>=1){
        s += __shfl_down_sync(0xffffffffu, s, off);
        q += __shfl_down_sync(0xffffffffu, q, off);
    }
    const int wid = threadIdx.x >> 5;
    if ((threadIdx.x & 31) == 0){ red[wid] = s; red[8+wid] = q; }
    __syncthreads();
    s = 0.f; q = 0.f;
#pragma unroll
    for (int i=0;i<8;i++){ s += red[i]; q += red[8+i]; }
    __syncthreads();
}

// ==== transpose+convert: [b][c][h][w] -> [inp][b][h][w][c] fp16; inp0 also -> g_bhi ====
__global__ __launch_bounds__(256) void xpose_cvt(const float* __restrict__ x,
    const float* __restrict__ xf, const float* __restrict__ xr)
{
    extern __shared__ float tl[];   // [128][133]
    const int inp = blockIdx.x, h = blockIdx.y, b = blockIdx.z;
    const float* src = inp==0 ? x : (inp==1 ? xf : xr);
    const int tid = threadIdx.x;
    const float* sp = src + (size_t)b*CHW + (size_t)h*128;
    for (int u = tid; u < 4096; u += 256){
        int c = u >> 5, q = u & 31;
        float4 v = *(const float4*)(sp + (size_t)c*HW + 4*q);
        float* d = tl + c*133 + 4*q;
        d[0]=v.x; d[1]=v.y; d[2]=v.z; d[3]=v.w;
    }
    __syncthreads();
    const size_t obase = ((size_t)inp*1024 + b*128 + h) * 16384;
    const size_t bbase = (((size_t)b*130 + (h+1))*130)*384;
    for (int u = tid; u < 4096; u += 256){
        int cg = u & 31, w = u >> 5;
        float v0 = tl[(4*cg+0)*133 + w], v1 = tl[(4*cg+1)*133 + w];
        float v2 = tl[(4*cg+2)*133 + w], v3 = tl[(4*cg+3)*133 + w];
        uint2 pv = make_uint2(pack_f16(v0, v1), pack_f16(v2, v3));
        *(uint2*)&g_tih[obase + (size_t)w*128 + 4*cg] = pv;
        if (inp == 0)
            *(uint2*)&g_bhi[bbase + (size_t)(w+1)*384 + 256 + 4*cg] = pv;
    }
}

// ==== compose 1x1 weights AND write fp16 panels directly ====================
__global__ __launch_bounds__(256) void wcompose_kernel(
    const float* __restrict__ Wx, const float* __restrict__ bx,
    const float* __restrict__ W1, const float* __restrict__ b1,
    const float* __restrict__ W2, const float* __restrict__ b2,
    const float* __restrict__ Wf, const float* __restrict__ bf,
    const float* __restrict__ Wr, const float* __restrict__ br_)
{
    extern __shared__ float S[];
    const int which = blockIdx.x, tid = threadIdx.x;
    if (which == 0 || which >= 3){
        const float* Ws = which==0 ? Wx : (which==3 ? Wf : Wr);
        const float* bs = which==0 ? bx : (which==3 ? bf : br_);
        for (int i = tid; i < 16384; i += 256){
            int o = i >> 7, c = i & 127;
            g_wsh[which*16384 + (c>>6)*8192 + o*64 + (c&63)] =
                __half_as_ushort(__float2half(Ws[i]));
        }
        if (tid < 128) g_bcf[which*128 + tid] = bs[tid];
        return;
    }
    const float* Wo = (which==1) ? W1 : W2;
    const float* bo = (which==1) ? b1 : b2;
    for (int i = tid; i < 16384; i += 256) S[i] = Wx[i];
    __syncthreads();
    int r = tid >> 1, c0 = (tid & 1) * 64;
    float acc[64];
#pragma unroll
    for (int j = 0; j < 64; j++) acc[j] = 0.f;
    for (int k = 0; k < 128; k++){
        float a = Wo[r*128 + k];
#pragma unroll
        for (int j = 0; j < 64; j++) acc[j] = fmaf(a, S[k*128 + c0 + j], acc[j]);
    }
    for (int j = 0; j < 64; j++)
        g_wsh[which*16384 + (tid&1)*8192 + r*64 + j] =
            __half_as_ushort(__float2half(acc[j]));
    if (tid < 128){
        float s = bo[tid];
        for (int k = 0; k < 128; k++) s = fmaf(Wo[tid*128 + k], bx[k], s);
        g_bcf[which*128 + tid] = s;
    }
}

// ==== FUSED front end: one CTA per (b,h) does 5 conv GEMMs + both attn branches ====
#define FXB  0u
#define FW0  32768u
#define FW1  65536u
#define FXP  98304u
#define FX1  131072u
#define FX2  163840u
#define FXF  196608u
#define FSMEM 229376

__global__ __launch_bounds__(256) void front_mma(void)
{
    extern __shared__ char dsm[];
    __shared__ float red[16];
    const int tid = threadIdx.x, l = tid & 31, wid = tid >> 5;
    const int mw = wid & 1, nw = wid >> 1;
    const int h = blockIdx.x, b = blockIdx.y;
    const uint32_t sb = smem_u32(dsm);

    auto stage_w = [&](int which, uint32_t off){
        const char* wH = (const char*)g_wsh + which*32768;
        for (int u = tid; u < 2048; u += 256){
            uint32_t d = off + (uint32_t)(u >> 10)*16384 + SWZ((uint32_t)((u & 1023)*16));
            CP16(sb + d, wH + u*16);
        }
    };
    auto stage_x = [&](int inp){
        const char* tH = (const char*)g_tih + ((size_t)inp*1024 + b*128 + h)*32768;
        for (int u = tid; u < 2048; u += 256){
            int w = u >> 4, j = u & 15;
            int pn = j >> 3, jj = j & 7;
            CP16(sb + FXB + pn*16384 + SWZ((uint32_t)(w*128 + jj*16)),
                 tH + w*256 + pn*128 + jj*16);
        }
    };

    float acc[4][4][4];
    auto zacc = [&](){
#pragma unroll
        for (int f=0;f<4;f++)
#pragma unroll
            for (int g=0;g<4;g++)
#pragma unroll
                for (int e=0;e<4;e++) acc[f][g][e] = 0.f;
    };
    auto conv_gemm = [&](uint32_t woff){
        zacc();
        gemm64f(sb, woff,         FXB,         l, mw, nw, acc);
        gemm64f(sb, woff + 16384, FXB + 16384, l, mw, nw, acc);
    };
    auto write_Apanels = [&](uint32_t doff, int which){
#pragma unroll
        for (int f = 0; f < 4; f++){
            int c1 = mw*64 + f*16 + (l>>2), c2 = c1 + 8;
            float b1v = g_bcf[which*128 + c1], b2v = g_bcf[which*128 + c2];
#pragma unroll
            for (int g = 0; g < 4; g++){
                int w = nw*32 + g*8 + 2*(l & 3);
                uint32_t pn = (uint32_t)(w >> 6)*16384;
                uint32_t byt = (uint32_t)((w & 63)*2);
                *(unsigned*)(dsm + doff + pn + SWZ((uint32_t)(c1*128) + byt)) =
                    pack_f16(acc[f][g][0] + b1v, acc[f][g][1] + b1v);
                *(unsigned*)(dsm + doff + pn + SWZ((uint32_t)(c2*128) + byt)) =
                    pack_f16(acc[f][g][2] + b2v, acc[f][g][3] + b2v);
            }
        }
    };
    auto write_xp = [&](){
#pragma unroll
        for (int f = 0; f < 4; f++){
            int d1 = mw*64 + f*16 + (l>>2), d2 = d1 + 8;
            float b1v = g_bcf[d1], b2v = g_bcf[d2];
            uint32_t p1 = (uint32_t)(d1 >> 6)*16384, y1 = (uint32_t)((d1 & 63)*2);
            uint32_t p2 = (uint32_t)(d2 >> 6)*16384, y2 = (uint32_t)((d2 & 63)*2);
#pragma unroll
            for (int g = 0; g < 4; g++){
                int w = nw*32 + g*8 + 2*(l & 3);
                *(unsigned short*)(dsm + FXP + p1 + SWZ((uint32_t)(w*128)     + y1)) =
                    __half_as_ushort(__float2half(acc[f][g][0] + b1v));
                *(unsigned short*)(dsm + FXP + p1 + SWZ((uint32_t)((w+1)*128) + y1)) =
                    __half_as_ushort(__float2half(acc[f][g][1] + b1v));
                *(unsigned short*)(dsm + FXP + p2 + SWZ((uint32_t)(w*128)     + y2)) =
                    __half_as_ushort(__float2half(acc[f][g][2] + b2v));
                *(unsigned short*)(dsm + FXP + p2 + SWZ((uint32_t)((w+1)*128) + y2)) =
                    __half_as_ushort(__float2half(acc[f][g][3] + b2v));
            }
        }
    };

    auto attn_branch = [&](uint32_t Aoff, uint32_t Boff, uint32_t scratch, int brIdx){
        zacc();
        gemm64f(sb, Aoff,         Boff,         l, mw, nw, acc);
        gemm64f(sb, Aoff + 16384, Boff + 16384, l, mw, nw, acc);
        float ls = 0.f, lq = 0.f;
#pragma unroll
        for (int f=0;f<4;f++)
#pragma unroll
            for (int g=0;g<4;g++)
#pragma unroll
                for (int e=0;e<4;e++){ ls += acc[f][g][e]; lq += acc[f][g][e]*acc[f][g][e]; }
        block_reduce_2(ls, lq, red);
        float mean = ls * (1.f/16384.f);
        float inv  = rsqrtf(lq * (1.f/16384.f) - mean*mean + EPSF);
#pragma unroll
        for (int f = 0; f < 4; f++){
            int c1 = mw*64 + f*16 + (l>>2), c2 = c1 + 8;
#pragma unroll
            for (int g = 0; g < 4; g++){
                int dd = nw*32 + g*8 + 2*(l & 3);
                uint32_t pn = (uint32_t)(dd >> 6)*16384;
                uint32_t byt = (uint32_t)((dd & 63)*2);
                *(unsigned*)(dsm + Aoff + pn + SWZ((uint32_t)(c1*128) + byt)) =
                    pack_f16((acc[f][g][0]-mean)*inv, (acc[f][g][1]-mean)*inv);
                *(unsigned*)(dsm + Aoff + pn + SWZ((uint32_t)(c2*128) + byt)) =
                    pack_f16((acc[f][g][2]-mean)*inv, (acc[f][g][3]-mean)*inv);
            }
        }
        __syncthreads();
        zacc();
        gemm64f(sb, Aoff,         FXP,         l, mw, nw, acc);
        gemm64f(sb, Aoff + 16384, FXP + 16384, l, mw, nw, acc);
        ls = 0.f; lq = 0.f;
#pragma unroll
        for (int f=0;f<4;f++)
#pragma unroll
            for (int g=0;g<4;g++)
#pragma unroll
                for (int e=0;e<4;e++){ ls += acc[f][g][e]; lq += acc[f][g][e]*acc[f][g][e]; }
        block_reduce_2(ls, lq, red);
        mean = ls * (1.f/16384.f);
        inv  = rsqrtf(lq * (1.f/16384.f) - mean*mean + EPSF);
        unsigned short* tile = (unsigned short*)(dsm + scratch);
#pragma unroll
        for (int f = 0; f < 4; f++){
            int c1 = mw*64 + f*16 + (l>>2), c2 = c1 + 8;
#pragma unroll
            for (int g = 0; g < 4; g++){
                int w = nw*32 + g*8 + 2*(l & 3);
                tile[(size_t)w*128 + c1]     = __half_as_ushort(__float2half((acc[f][g][0]-mean)*inv));
                tile[(size_t)(w+1)*128 + c1] = __half_as_ushort(__float2half((acc[f][g][1]-mean)*inv));
                tile[(size_t)w*128 + c2]     = __half_as_ushort(__float2half((acc[f][g][2]-mean)*inv));
                tile[(size_t)(w+1)*128 + c2] = __half_as_ushort(__float2half((acc[f][g][3]-mean)*inv));
            }
        }
        __syncthreads();
        const size_t rowb = (((size_t)b*130 + (h+1))*130 + 1)*384 + brIdx*128;
        for (int u = tid; u < 2048; u += 256){
            int w = u >> 4, j = u & 15;
            uint4 v = *(uint4*)(dsm + scratch + w*256 + j*16);
            *(uint4*)((char*)g_bhi + (rowb + (size_t)w*384)*2 + j*16) = v;
        }
        __syncthreads();
    };

    stage_x(0); stage_w(0, FW0); CP_COMMIT();
    stage_w(1, FW1); CP_COMMIT();

    CP_WAIT1(); __syncthreads();
    conv_gemm(FW0); write_xp();
    __syncthreads();
    stage_w(2, FW0); CP_COMMIT();

    CP_WAIT1(); __syncthreads();
    conv_gemm(FW1); write_Apanels(FX1, 1);
    __syncthreads();
    stage_w(3, FW1); CP_COMMIT();

    CP_WAIT1(); __syncthreads();
    conv_gemm(FW0); write_Apanels(FX2, 2);
    __syncthreads();
    stage_x(1); CP_COMMIT();
    stage_w(4, FW0); CP_COMMIT();

    CP_WAIT1(); __syncthreads();
    conv_gemm(FW1); write_Apanels(FXF, 3);
    __syncthreads();
    stage_x(2); CP_COMMIT();

    attn_branch(FX1, FXF, FXF, 0);

    CP_WAIT0(); __syncthreads();
    conv_gemm(FW0); write_Apanels(FX1, 4);
    __syncthreads();

    attn_branch(FX2, FX1, FX1, 1);
}

// ============ conv3x3 weight prep: fp16 [tap][chunk][o][ci] =================
__global__ void presplit_kernel(const float* __restrict__ Wm)
{
    int idx = blockIdx.x*256 + threadIdx.x;
    if (idx >= 9*6*384*64) return;
    int ci = idx & 63;
    int o  = (idx >> 6) % 384;
    int r  = idx >> 6; r /= 384;
    int chunk = r % 6, tap = r / 6;
    float v = Wm[(size_t)o*3456 + (chunk*64 + ci)*9 + tap];
    g_wh[idx] = __half_as_ushort(__float2half(v));
}

// ====== conv3x3 fp16, PERSISTENT, 128 thr, cross-boundary frag pipeline ======
// step i: outer s = (i%54)/3 -> (kh, chunk), inner kw = i%3.
// A ring: 4 x 16KB (slot i&3). B ring: 2 x 16640B (slot (i/3)&1).
#define STG_A  16384
#define STG_B  16640
#define OFFB   65536
#define SMEM3  98816
#define NTILE  3072
#define NCTA   296

__global__ __launch_bounds__(128, 2) void conv3x3_tc(
    const float* __restrict__ bm, const float* __restrict__ gamma,
    const float* __restrict__ beta, const float* __restrict__ rmean,
    const float* __restrict__ rvar, float* __restrict__ out)
{
    extern __shared__ char dsm[];
    const int tid = threadIdx.x, l = tid & 31, wid = tid >> 5;
    const int mw = wid & 1, nw = wid >> 1;
    const int bx = blockIdx.x;
    const uint32_t sb = smem_u32(dsm);

    const int nt = (NTILE - bx + NCTA - 1) / NCTA;
    const int total = nt * 54;

    auto stageA = [&](int idx){
        int tile = bx + (idx / 54) * NCTA;
        int j = idx % 54;
        int s = j / 3, kw_ = j % 3;
        int kh = s / 6, chunk = s - kh*6;
        int tap = kh*3 + kw_;
        int o0 = (tile % 3) << 7;
        uint32_t s0 = sb + (uint32_t)(idx & 3)*STG_A;
        const char* srcA = (const char*)g_wh + (((size_t)tap*6 + chunk)*384 + o0)*128;
        for (int u = tid; u < 1024; u += 128)
            CP16(s0 + SWZ(u*16), srcA + u*16);
    };
    auto stageB = [&](int idx){                 // only when idx % 3 == 0
        int tile = bx + (idx / 54) * NCTA;
        int s = (idx % 54) / 3;
        int kh = s / 6, chunk = s - kh*6;
        int r = tile / 3;
        int h = r & 127, b2 = r >> 7;
        uint32_t s0 = sb + OFFB + (uint32_t)((idx/3) & 1)*STG_B;
        size_t rowbase = ((size_t)b2*130 + (h+kh))*130*768 + (size_t)chunk*128;
        const char* BH = (const char*)g_bhi;
        for (int u = tid; u < 1040; u += 128){
            int wp = u >> 3, jj = u & 7;
            CP16(s0 + SWZ(wp*128 + jj*16), BH + rowbase + (size_t)wp*768 + jj*16);
        }
    };

    float acc[4][8][4];
    uint32_t ahA[4][4], bhA[8][2], ahB[4][4], bhB[8][2];

    // load fragments for flat step t = 4*i + ks into (ahd, bhd)
    auto loadfrag = [&](int t, uint32_t (*ahd)[4], uint32_t (*bhd)[2]){
        const int ii = t >> 2, ks = t & 3;
        const int kw_ = (ii % 54) % 3;
        const uint32_t sA = sb + (uint32_t)(ii & 3)*STG_A;
        const uint32_t sB = sb + OFFB + (uint32_t)((ii/3) & 1)*STG_B;
        const uint32_t abyte = (uint32_t)(ks*32) + ((l>>4)<<4);
#pragma unroll
        for (int f = 0; f < 4; f++){
            int row = mw*64 + f*16 + (l & 15);
            uint32_t off = SWZ((uint32_t)(row*128) + abyte);
            LDSM4(ahd[f][0],ahd[f][1],ahd[f][2],ahd[f][3], sA + off);
        }
        const uint32_t bbyte = (uint32_t)(ks*32) + (((l>>3)&1)<<4);
#pragma unroll
        for (int g2 = 0; g2 < 4; g2++){
            int rowb = nw*64 + g2*16 + kw_ + (l & 7) + ((l>>4)<<3);
            uint32_t off = SWZ((uint32_t)(rowb*128) + bbyte);
            uint32_t t0,t1,t2,t3;
            LDSM4(t0,t1,t2,t3, sB + off);
            bhd[g2*2][0]=t0; bhd[g2*2][1]=t1;
            bhd[g2*2+1][0]=t2; bhd[g2*2+1][1]=t3;
        }
    };
    auto mmab = [&](uint32_t (*ahd)[4], uint32_t (*bhd)[2]){
#pragma unroll
        for (int f = 0; f < 4; f++)
#pragma unroll
            for (int g = 0; g < 8; g++)
                MMAF16(acc[f][g], ahd[f], bhd[g]);
    };

    stageA(0); stageB(0); CP_COMMIT();
    stageA(1); CP_COMMIT();
    stageA(2); CP_COMMIT();
    CP_WAIT1(); __syncthreads();       // groups 0,1 complete: slots 0,1 + B0 ready
    loadfrag(0, ahA, bhA);

    for (int i = 0; i < total; i++){
        if (i > 0){
            if (i <= total - 3) CP_WAIT1(); else CP_WAIT0();
            __syncthreads();
        }
        if (i + 3 < total){
            stageA(i+3);
            if (((i+3) % 3) == 0) stageB(i+3);
            CP_COMMIT();
        }
        const int j = i % 54;
        if (j == 0){
#pragma unroll
            for (int f=0;f<4;f++)
#pragma unroll
                for (int g=0;g<8;g++)
#pragma unroll
                    for (int e=0;e<4;e++) acc[f][g][e] = 0.f;
        }
        const int t0 = 4*i;
        loadfrag(t0+1, ahB, bhB);  mmab(ahA, bhA);
        loadfrag(t0+2, ahA, bhA);  mmab(ahB, bhB);
        loadfrag(t0+3, ahB, bhB);  mmab(ahA, bhA);
        if (t0 + 4 < 4*total) loadfrag(t0+4, ahA, bhA);   // cross-boundary preload
        mmab(ahB, bhB);

        if (j == 53){
            int tile = bx + (i / 54) * NCTA;
            int o0 = (tile % 3) << 7;
            int r = tile / 3;
            int h = r & 127, b2 = r >> 7;
#pragma unroll
            for (int f = 0; f < 4; f++){
                int o1 = o0 + mw*64 + f*16 + (l >> 2);
                int o2 = o1 + 8;
                float sc1 = gamma[o1] * rsqrtf(rvar[o1] + EPSF);
                float sh1 = beta[o1] + (bm[o1] - rmean[o1]) * sc1;
                float sc2 = gamma[o2] * rsqrtf(rvar[o2] + EPSF);
                float sh2 = beta[o2] + (bm[o2] - rmean[o2]) * sc2;
                float* r1 = out + ((size_t)(b2*384 + o1))*HW + (size_t)h*128;
                float* r2 = out + ((size_t)(b2*384 + o2))*HW + (size_t)h*128;
#pragma unroll
                for (int g = 0; g < 8; g++){
                    int w = nw*64 + g*8 + 2*(l & 3);
                    float2 v1, v2;
                    v1.x = fmaxf(fmaf(acc[f][g][0], sc1, sh1), 0.f);
                    v1.y = fmaxf(fmaf(acc[f][g][1], sc1, sh1), 0.f);
                    v2.x = fmaxf(fmaf(acc[f][g][2], sc2, sh2), 0.f);
                    v2.y = fmaxf(fmaf(acc[f][g][3], sc2, sh2), 0.f);
                    *(float2*)(r1 + w) = v1;
                    *(float2*)(r2 + w) = v2;
                }
            }
        }
    }
}

// =============================================================================
extern "C" void kernel_launch(void* const* d_in, const int* in_sizes, int n_in,
                              void* d_out, int out_size)
{
    const float* x  = (const float*)d_in[0];
    const float* xf = (const float*)d_in[1];
    const float* xr = (const float*)d_in[2];
    const float* Wx = (const float*)d_in[3];
    const float* bx = (const float*)d_in[4];
    const float* W1 = (const float*)d_in[5];
    const float* b1 = (const float*)d_in[6];
    const float* W2 = (const float*)d_in[7];
    const float* b2 = (const float*)d_in[8];
    const float* Wf = (const float*)d_in[9];
    const float* bf = (const float*)d_in[10];
    const float* Wr = (const float*)d_in[11];
    const float* br_ = (const float*)d_in[12];
    const float* Wm = (const float*)d_in[13];
    const float* bm = (const float*)d_in[14];
    const float* gamma = (const float*)d_in[15];
    const float* beta  = (const float*)d_in[16];
    const float* rmean = (const float*)d_in[17];
    const float* rvar  = (const float*)d_in[18];
    float* out = (float*)d_out;

    cudaFuncSetAttribute(xpose_cvt,   cudaFuncAttributeMaxDynamicSharedMemorySize, 68096);
    cudaFuncSetAttribute(wcompose_kernel, cudaFuncAttributeMaxDynamicSharedMemorySize, 65536);
    cudaFuncSetAttribute(front_mma,   cudaFuncAttributeMaxDynamicSharedMemorySize, FSMEM);
    cudaFuncSetAttribute(conv3x3_tc,  cudaFuncAttributeMaxDynamicSharedMemorySize, SMEM3);

    xpose_cvt<<<dim3(3, 128, 8), 256, 68096>>>(x, xf, xr);
    wcompose_kernel<<<5, 256, 65536>>>(Wx, bx, W1, b1, W2, b2, Wf, bf, Wr, br_);
    front_mma<<<dim3(128, 8), 256, FSMEM>>>();
    presplit_kernel<<<5184, 256>>>(Wm);
    conv3x3_tc<<<NCTA, 128, SMEM3>>>(bm, gamma, beta, rmean, rvar, out);
}

// round 17
// speedup vs baseline: 1.1503x; 1.1503x over previous
#include <cuda_runtime.h>
#include <cuda_bf16.h>
#include <cuda_fp16.h>
#include <cstdint>

#define EPSF 1e-5f
#define HW   16384
#define CHW  2097152

// ---------------- scratch (static device memory) ----------------
__device__ float g_bcf[5*128];                          // composed biases
__device__ __align__(16) unsigned short g_wsh[5*2*128*64];   // fp16 [which][pn][o][ci64]
__device__ __align__(16) unsigned short g_tih[3ull*8*CHW];   // fp16 inputs T: [inp][b][h][w][c]
__device__ unsigned short g_wh[9*6*384*64];             // conv3x3 W fp16: [tap][chunk][o][ci]
__device__ unsigned short g_bhi[8ull*130*130*384];      // conv3x3 in fp16: [b][hp][wp][ci]

// ---------------- helpers ----------------
__device__ __forceinline__ uint32_t smem_u32(const void* p){
    uint32_t a; asm("{ .reg .u64 t; cvta.to.shared.u64 t, %1; cvt.u32.u64 %0, t; }"
                    : "=r"(a) : "l"(p)); return a;
}
#define SWZ(x) ((x) ^ (((x)>>3)&0x70))
#define CP16(dst, src) asm volatile("cp.async.cg.shared.global [%0], [%1], 16;" \
    :: "r"((uint32_t)(dst)), "l"((const void*)(src)) : "memory")
#define CP_COMMIT() asm volatile("cp.async.commit_group;" ::: "memory")
#define CP_WAIT0()  asm volatile("cp.async.wait_group 0;" ::: "memory")
#define CP_WAIT1()  asm volatile("cp.async.wait_group 1;" ::: "memory")
#define CP_WAIT2()  asm volatile("cp.async.wait_group 2;" ::: "memory")
#define LDSM4(r0,r1,r2,r3,a) asm volatile( \
    "ldmatrix.sync.aligned.m8n8.x4.shared.b16 {%0,%1,%2,%3}, [%4];" \
    : "=r"(r0),"=r"(r1),"=r"(r2),"=r"(r3) : "r"(a))
#define MMAF16(c,a,b) asm volatile( \
    "mma.sync.aligned.m16n8k16.row.col.f32.f16.f16.f32 " \
    "{%0,%1,%2,%3},{%4,%5,%6,%7},{%8,%9},{%0,%1,%2,%3};" \
    : "+f"((c)[0]),"+f"((c)[1]),"+f"((c)[2]),"+f"((c)[3]) \
    : "r"((a)[0]),"r"((a)[1]),"r"((a)[2]),"r"((a)[3]), "r"((b)[0]),"r"((b)[1]))

__device__ __forceinline__ unsigned pack_f16(float v0, float v1){
    unsigned hp; asm("cvt.rn.f16x2.f32 %0, %1, %2;" : "=r"(hp) : "f"(v1), "f"(v0));
    return hp;
}

// 128x128x64 GEMM chunk, single-pass fp16, ks-pipelined fragment loads.
__device__ __forceinline__ void gemm64f(uint32_t sb, uint32_t a0, uint32_t b0,
                                        int l, int mw, int nw, float acc[4][4][4])
{
    uint32_t ah[2][4][4], bh[2][4][2];
    auto loadf = [&](int ks, int buf){
        const uint32_t abyte = (uint32_t)(ks*32) + ((l>>4)<<4);
#pragma unroll
        for (int f = 0; f < 4; f++){
            int row = mw*64 + f*16 + (l & 15);
            uint32_t off = SWZ((uint32_t)(row*128) + abyte);
            LDSM4(ah[buf][f][0],ah[buf][f][1],ah[buf][f][2],ah[buf][f][3], sb + a0 + off);
        }
        const uint32_t bbyte = (uint32_t)(ks*32) + (((l>>3)&1)<<4);
#pragma unroll
        for (int g2 = 0; g2 < 2; g2++){
            int rowb = nw*32 + g2*16 + (l & 7) + ((l>>4)<<3);
            uint32_t off = SWZ((uint32_t)(rowb*128) + bbyte);
            uint32_t t0,t1,t2,t3;
            LDSM4(t0,t1,t2,t3, sb + b0 + off);
            bh[buf][g2*2][0]=t0; bh[buf][g2*2][1]=t1;
            bh[buf][g2*2+1][0]=t2; bh[buf][g2*2+1][1]=t3;
        }
    };
    loadf(0, 0);
#pragma unroll
    for (int ks = 0; ks < 4; ks++){
        const int cur = ks & 1;
        if (ks < 3) loadf(ks+1, cur^1);
#pragma unroll
        for (int f = 0; f < 4; f++)
#pragma unroll
            for (int g = 0; g < 4; g++)
                MMAF16(acc[f][g], ah[cur][f], bh[cur][g]);
    }
}

__device__ __forceinline__ void block_reduce_2(float& s, float& q, float* red)
{
#pragma unroll
    for (int off=16; off>0; off>>=1){
        s += __shfl_down_sync(0xffffffffu, s, off);
        q += __shfl_down_sync(0xffffffffu, q, off);
    }
    const int wid = threadIdx.x >> 5;
    if ((threadIdx.x & 31) == 0){ red[wid] = s; red[8+wid] = q; }
    __syncthreads();
    s = 0.f; q = 0.f;
#pragma unroll
    for (int i=0;i<8;i++){ s += red[i]; q += red[8+i]; }
    __syncthreads();
}

// ==== transpose+convert: [b][c][h][w] -> [inp][b][h][w][c] fp16; inp0 also -> g_bhi ====
__global__ __launch_bounds__(256) void xpose_cvt(const float* __restrict__ x,
    const float* __restrict__ xf, const float* __restrict__ xr)
{
    extern __shared__ float tl[];   // [128][133]
    const int inp = blockIdx.x, h = blockIdx.y, b = blockIdx.z;
    const float* src = inp==0 ? x : (inp==1 ? xf : xr);
    const int tid = threadIdx.x;
    const float* sp = src + (size_t)b*CHW + (size_t)h*128;
    for (int u = tid; u < 4096; u += 256){
        int c = u >> 5, q = u & 31;
        float4 v = *(const float4*)(sp + (size_t)c*HW + 4*q);
        float* d = tl + c*133 + 4*q;
        d[0]=v.x; d[1]=v.y; d[2]=v.z; d[3]=v.w;
    }
    __syncthreads();
    const size_t obase = ((size_t)inp*1024 + b*128 + h) * 16384;
    const size_t bbase = (((size_t)b*130 + (h+1))*130)*384;
    for (int u = tid; u < 4096; u += 256){
        int cg = u & 31, w = u >> 5;
        float v0 = tl[(4*cg+0)*133 + w], v1 = tl[(4*cg+1)*133 + w];
        float v2 = tl[(4*cg+2)*133 + w], v3 = tl[(4*cg+3)*133 + w];
        uint2 pv = make_uint2(pack_f16(v0, v1), pack_f16(v2, v3));
        *(uint2*)&g_tih[obase + (size_t)w*128 + 4*cg] = pv;
        if (inp == 0)
            *(uint2*)&g_bhi[bbase + (size_t)(w+1)*384 + 256 + 4*cg] = pv;
    }
}

// ==== compose 1x1 weights AND write fp16 panels directly ====================
__global__ __launch_bounds__(256) void wcompose_kernel(
    const float* __restrict__ Wx, const float* __restrict__ bx,
    const float* __restrict__ W1, const float* __restrict__ b1,
    const float* __restrict__ W2, const float* __restrict__ b2,
    const float* __restrict__ Wf, const float* __restrict__ bf,
    const float* __restrict__ Wr, const float* __restrict__ br_)
{
    extern __shared__ float S[];
    const int which = blockIdx.x, tid = threadIdx.x;
    if (which == 0 || which >= 3){
        const float* Ws = which==0 ? Wx : (which==3 ? Wf : Wr);
        const float* bs = which==0 ? bx : (which==3 ? bf : br_);
        for (int i = tid; i < 16384; i += 256){
            int o = i >> 7, c = i & 127;
            g_wsh[which*16384 + (c>>6)*8192 + o*64 + (c&63)] =
                __half_as_ushort(__float2half(Ws[i]));
        }
        if (tid < 128) g_bcf[which*128 + tid] = bs[tid];
        return;
    }
    const float* Wo = (which==1) ? W1 : W2;
    const float* bo = (which==1) ? b1 : b2;
    for (int i = tid; i < 16384; i += 256) S[i] = Wx[i];
    __syncthreads();
    int r = tid >> 1, c0 = (tid & 1) * 64;
    float acc[64];
#pragma unroll
    for (int j = 0; j < 64; j++) acc[j] = 0.f;
    for (int k = 0; k < 128; k++){
        float a = Wo[r*128 + k];
#pragma unroll
        for (int j = 0; j < 64; j++) acc[j] = fmaf(a, S[k*128 + c0 + j], acc[j]);
    }
    for (int j = 0; j < 64; j++)
        g_wsh[which*16384 + (tid&1)*8192 + r*64 + j] =
            __half_as_ushort(__float2half(acc[j]));
    if (tid < 128){
        float s = bo[tid];
        for (int k = 0; k < 128; k++) s = fmaf(Wo[tid*128 + k], bx[k], s);
        g_bcf[which*128 + tid] = s;
    }
}

// ==== FUSED front end: one CTA per (b,h) does 5 conv GEMMs + both attn branches ====
#define FXB  0u
#define FW0  32768u
#define FW1  65536u
#define FXP  98304u
#define FX1  131072u
#define FX2  163840u
#define FXF  196608u
#define FSMEM 229376

__global__ __launch_bounds__(256) void front_mma(void)
{
    extern __shared__ char dsm[];
    __shared__ float red[16];
    const int tid = threadIdx.x, l = tid & 31, wid = tid >> 5;
    const int mw = wid & 1, nw = wid >> 1;
    const int h = blockIdx.x, b = blockIdx.y;
    const uint32_t sb = smem_u32(dsm);

    auto stage_w = [&](int which, uint32_t off){
        const char* wH = (const char*)g_wsh + which*32768;
        for (int u = tid; u < 2048; u += 256){
            uint32_t d = off + (uint32_t)(u >> 10)*16384 + SWZ((uint32_t)((u & 1023)*16));
            CP16(sb + d, wH + u*16);
        }
    };
    auto stage_x = [&](int inp){
        const char* tH = (const char*)g_tih + ((size_t)inp*1024 + b*128 + h)*32768;
        for (int u = tid; u < 2048; u += 256){
            int w = u >> 4, j = u & 15;
            int pn = j >> 3, jj = j & 7;
            CP16(sb + FXB + pn*16384 + SWZ((uint32_t)(w*128 + jj*16)),
                 tH + w*256 + pn*128 + jj*16);
        }
    };

    float acc[4][4][4];
    auto zacc = [&](){
#pragma unroll
        for (int f=0;f<4;f++)
#pragma unroll
            for (int g=0;g<4;g++)
#pragma unroll
                for (int e=0;e<4;e++) acc[f][g][e] = 0.f;
    };
    auto conv_gemm = [&](uint32_t woff){
        zacc();
        gemm64f(sb, woff,         FXB,         l, mw, nw, acc);
        gemm64f(sb, woff + 16384, FXB + 16384, l, mw, nw, acc);
    };
    auto write_Apanels = [&](uint32_t doff, int which){
#pragma unroll
        for (int f = 0; f < 4; f++){
            int c1 = mw*64 + f*16 + (l>>2), c2 = c1 + 8;
            float b1v = g_bcf[which*128 + c1], b2v = g_bcf[which*128 + c2];
#pragma unroll
            for (int g = 0; g < 4; g++){
                int w = nw*32 + g*8 + 2*(l & 3);
                uint32_t pn = (uint32_t)(w >> 6)*16384;
                uint32_t byt = (uint32_t)((w & 63)*2);
                *(unsigned*)(dsm + doff + pn + SWZ((uint32_t)(c1*128) + byt)) =
                    pack_f16(acc[f][g][0] + b1v, acc[f][g][1] + b1v);
                *(unsigned*)(dsm + doff + pn + SWZ((uint32_t)(c2*128) + byt)) =
                    pack_f16(acc[f][g][2] + b2v, acc[f][g][3] + b2v);
            }
        }
    };
    auto write_xp = [&](){
#pragma unroll
        for (int f = 0; f < 4; f++){
            int d1 = mw*64 + f*16 + (l>>2), d2 = d1 + 8;
            float b1v = g_bcf[d1], b2v = g_bcf[d2];
            uint32_t p1 = (uint32_t)(d1 >> 6)*16384, y1 = (uint32_t)((d1 & 63)*2);
            uint32_t p2 = (uint32_t)(d2 >> 6)*16384, y2 = (uint32_t)((d2 & 63)*2);
#pragma unroll
            for (int g = 0; g < 4; g++){
                int w = nw*32 + g*8 + 2*(l & 3);
                *(unsigned short*)(dsm + FXP + p1 + SWZ((uint32_t)(w*128)     + y1)) =
                    __half_as_ushort(__float2half(acc[f][g][0] + b1v));
                *(unsigned short*)(dsm + FXP + p1 + SWZ((uint32_t)((w+1)*128) + y1)) =
                    __half_as_ushort(__float2half(acc[f][g][1] + b1v));
                *(unsigned short*)(dsm + FXP + p2 + SWZ((uint32_t)(w*128)     + y2)) =
                    __half_as_ushort(__float2half(acc[f][g][2] + b2v));
                *(unsigned short*)(dsm + FXP + p2 + SWZ((uint32_t)((w+1)*128) + y2)) =
                    __half_as_ushort(__float2half(acc[f][g][3] + b2v));
            }
        }
    };

    auto attn_branch = [&](uint32_t Aoff, uint32_t Boff, uint32_t scratch, int brIdx){
        zacc();
        gemm64f(sb, Aoff,         Boff,         l, mw, nw, acc);
        gemm64f(sb, Aoff + 16384, Boff + 16384, l, mw, nw, acc);
        float ls = 0.f, lq = 0.f;
#pragma unroll
        for (int f=0;f<4;f++)
#pragma unroll
            for (int g=0;g<4;g++)
#pragma unroll
                for (int e=0;e<4;e++){ ls += acc[f][g][e]; lq += acc[f][g][e]*acc[f][g][e]; }
        block_reduce_2(ls, lq, red);
        float mean = ls * (1.f/16384.f);
        float inv  = rsqrtf(lq * (1.f/16384.f) - mean*mean + EPSF);
#pragma unroll
        for (int f = 0; f < 4; f++){
            int c1 = mw*64 + f*16 + (l>>2), c2 = c1 + 8;
#pragma unroll
            for (int g = 0; g < 4; g++){
                int dd = nw*32 + g*8 + 2*(l & 3);
                uint32_t pn = (uint32_t)(dd >> 6)*16384;
                uint32_t byt = (uint32_t)((dd & 63)*2);
                *(unsigned*)(dsm + Aoff + pn + SWZ((uint32_t)(c1*128) + byt)) =
                    pack_f16((acc[f][g][0]-mean)*inv, (acc[f][g][1]-mean)*inv);
                *(unsigned*)(dsm + Aoff + pn + SWZ((uint32_t)(c2*128) + byt)) =
                    pack_f16((acc[f][g][2]-mean)*inv, (acc[f][g][3]-mean)*inv);
            }
        }
        __syncthreads();
        zacc();
        gemm64f(sb, Aoff,         FXP,         l, mw, nw, acc);
        gemm64f(sb, Aoff + 16384, FXP + 16384, l, mw, nw, acc);
        ls = 0.f; lq = 0.f;
#pragma unroll
        for (int f=0;f<4;f++)
#pragma unroll
            for (int g=0;g<4;g++)
#pragma unroll
                for (int e=0;e<4;e++){ ls += acc[f][g][e]; lq += acc[f][g][e]*acc[f][g][e]; }
        block_reduce_2(ls, lq, red);
        mean = ls * (1.f/16384.f);
        inv  = rsqrtf(lq * (1.f/16384.f) - mean*mean + EPSF);
        unsigned short* tile = (unsigned short*)(dsm + scratch);
#pragma unroll
        for (int f = 0; f < 4; f++){
            int c1 = mw*64 + f*16 + (l>>2), c2 = c1 + 8;
#pragma unroll
            for (int g = 0; g < 4; g++){
                int w = nw*32 + g*8 + 2*(l & 3);
                tile[(size_t)w*128 + c1]     = __half_as_ushort(__float2half((acc[f][g][0]-mean)*inv));
                tile[(size_t)(w+1)*128 + c1] = __half_as_ushort(__float2half((acc[f][g][1]-mean)*inv));
                tile[(size_t)w*128 + c2]     = __half_as_ushort(__float2half((acc[f][g][2]-mean)*inv));
                tile[(size_t)(w+1)*128 + c2] = __half_as_ushort(__float2half((acc[f][g][3]-mean)*inv));
            }
        }
        __syncthreads();
        const size_t rowb = (((size_t)b*130 + (h+1))*130 + 1)*384 + brIdx*128;
        for (int u = tid; u < 2048; u += 256){
            int w = u >> 4, j = u & 15;
            uint4 v = *(uint4*)(dsm + scratch + w*256 + j*16);
            *(uint4*)((char*)g_bhi + (rowb + (size_t)w*384)*2 + j*16) = v;
        }
        __syncthreads();
    };

    stage_x(0); stage_w(0, FW0); CP_COMMIT();
    stage_w(1, FW1); CP_COMMIT();

    CP_WAIT1(); __syncthreads();
    conv_gemm(FW0); write_xp();
    __syncthreads();
    stage_w(2, FW0); CP_COMMIT();

    CP_WAIT1(); __syncthreads();
    conv_gemm(FW1); write_Apanels(FX1, 1);
    __syncthreads();
    stage_w(3, FW1); CP_COMMIT();

    CP_WAIT1(); __syncthreads();
    conv_gemm(FW0); write_Apanels(FX2, 2);
    __syncthreads();
    stage_x(1); CP_COMMIT();
    stage_w(4, FW0); CP_COMMIT();

    CP_WAIT1(); __syncthreads();
    conv_gemm(FW1); write_Apanels(FXF, 3);
    __syncthreads();
    stage_x(2); CP_COMMIT();

    attn_branch(FX1, FXF, FXF, 0);

    CP_WAIT0(); __syncthreads();
    conv_gemm(FW0); write_Apanels(FX1, 4);
    __syncthreads();

    attn_branch(FX2, FX1, FX1, 1);
}

// ============ conv3x3 weight prep: fp16 [tap][chunk][o][ci] =================
__global__ void presplit_kernel(const float* __restrict__ Wm)
{
    int idx = blockIdx.x*256 + threadIdx.x;
    if (idx >= 9*6*384*64) return;
    int ci = idx & 63;
    int o  = (idx >> 6) % 384;
    int r  = idx >> 6; r /= 384;
    int chunk = r % 6, tap = r / 6;
    float v = Wm[(size_t)o*3456 + (chunk*64 + ci)*9 + tap];
    g_wh[idx] = __half_as_ushort(__float2half(v));
}

// ====== conv3x3 fp16, PERSISTENT, 128 thr (R15-validated), B reused over kw ======
// step i: outer s = (i%54)/3 -> (kh, chunk), inner kw = i%3.
// A ring: 4 x 16KB (slot i&3). B ring: 2 x 16640B (slot (i/3)&1). ks-pipelined frags.
#define STG_A  16384
#define STG_B  16640
#define OFFB   65536
#define SMEM3  98816
#define NTILE  3072
#define NCTA   296

__global__ __launch_bounds__(128, 2) void conv3x3_tc(
    const float* __restrict__ bm, const float* __restrict__ gamma,
    const float* __restrict__ beta, const float* __restrict__ rmean,
    const float* __restrict__ rvar, float* __restrict__ out)
{
    extern __shared__ char dsm[];
    const int tid = threadIdx.x, l = tid & 31, wid = tid >> 5;
    const int mw = wid & 1, nw = wid >> 1;
    const int bx = blockIdx.x;
    const uint32_t sb = smem_u32(dsm);

    const int nt = (NTILE - bx + NCTA - 1) / NCTA;
    const int total = nt * 54;

    auto stageA = [&](int idx){
        int tile = bx + (idx / 54) * NCTA;
        int j = idx % 54;
        int s = j / 3, kw_ = j % 3;
        int kh = s / 6, chunk = s - kh*6;
        int tap = kh*3 + kw_;
        int o0 = (tile % 3) << 7;
        uint32_t s0 = sb + (uint32_t)(idx & 3)*STG_A;
        const char* srcA = (const char*)g_wh + (((size_t)tap*6 + chunk)*384 + o0)*128;
        for (int u = tid; u < 1024; u += 128)
            CP16(s0 + SWZ(u*16), srcA + u*16);
    };
    auto stageB = [&](int idx){                 // only called when idx % 3 == 0
        int tile = bx + (idx / 54) * NCTA;
        int s = (idx % 54) / 3;
        int kh = s / 6, chunk = s - kh*6;
        int r = tile / 3;
        int h = r & 127, b2 = r >> 7;
        uint32_t s0 = sb + OFFB + (uint32_t)((idx/3) & 1)*STG_B;
        size_t rowbase = ((size_t)b2*130 + (h+kh))*130*768 + (size_t)chunk*128;
        const char* BH = (const char*)g_bhi;
        for (int u = tid; u < 1040; u += 128){
            int wp = u >> 3, jj = u & 7;
            CP16(s0 + SWZ(wp*128 + jj*16), BH + rowbase + (size_t)wp*768 + jj*16);
        }
    };

    float acc[4][8][4];

    stageA(0); stageB(0); CP_COMMIT();
    stageA(1); CP_COMMIT();
    stageA(2); CP_COMMIT();

    for (int i = 0; i < total; i++){
        const int rem = total - 1 - i;
        if (rem >= 2) CP_WAIT2(); else if (rem == 1) CP_WAIT1(); else CP_WAIT0();
        __syncthreads();

        // issue next stage early so cp.async overlaps the MMA burst
        if (i + 3 < total){
            stageA(i+3);
            if (((i+3) % 3) == 0) stageB(i+3);
            CP_COMMIT();
        }

        const int j = i % 54;
        const int kw = j % 3;
        if (j == 0){
#pragma unroll
            for (int f=0;f<4;f++)
#pragma unroll
                for (int g=0;g<8;g++)
#pragma unroll
                    for (int e=0;e<4;e++) acc[f][g][e] = 0.f;
        }

        const uint32_t sA = sb + (uint32_t)(i & 3)*STG_A;
        const uint32_t sB = sb + OFFB + (uint32_t)((i/3) & 1)*STG_B;

        uint32_t ah[2][4][4], bh[2][8][2];
        auto load3 = [&](int ks, int buf){
            const uint32_t abyte = (uint32_t)(ks*32) + ((l>>4)<<4);
#pragma unroll
            for (int f = 0; f < 4; f++){
                int row = mw*64 + f*16 + (l & 15);
                uint32_t off = SWZ((uint32_t)(row*128) + abyte);
                LDSM4(ah[buf][f][0],ah[buf][f][1],ah[buf][f][2],ah[buf][f][3], sA + off);
            }
            const uint32_t bbyte = (uint32_t)(ks*32) + (((l>>3)&1)<<4);
#pragma unroll
            for (int g2 = 0; g2 < 4; g2++){
                int rowb = nw*64 + g2*16 + kw + (l & 7) + ((l>>4)<<3);
                uint32_t off = SWZ((uint32_t)(rowb*128) + bbyte);
                uint32_t t0,t1,t2,t3;
                LDSM4(t0,t1,t2,t3, sB + off);
                bh[buf][g2*2][0]=t0; bh[buf][g2*2][1]=t1;
                bh[buf][g2*2+1][0]=t2; bh[buf][g2*2+1][1]=t3;
            }
        };
        load3(0, 0);
#pragma unroll
        for (int ks = 0; ks < 4; ks++){
            const int cur = ks & 1;
            if (ks < 3) load3(ks+1, cur^1);
#pragma unroll
            for (int f = 0; f < 4; f++)
#pragma unroll
                for (int g = 0; g < 8; g++)
                    MMAF16(acc[f][g], ah[cur][f], bh[cur][g]);
        }

        if (j == 53){
            int tile = bx + (i / 54) * NCTA;
            int o0 = (tile % 3) << 7;
            int r = tile / 3;
            int h = r & 127, b2 = r >> 7;
#pragma unroll
            for (int f = 0; f < 4; f++){
                int o1 = o0 + mw*64 + f*16 + (l >> 2);
                int o2 = o1 + 8;
                float sc1 = gamma[o1] * rsqrtf(rvar[o1] + EPSF);
                float sh1 = beta[o1] + (bm[o1] - rmean[o1]) * sc1;
                float sc2 = gamma[o2] * rsqrtf(rvar[o2] + EPSF);
                float sh2 = beta[o2] + (bm[o2] - rmean[o2]) * sc2;
                float* r1 = out + ((size_t)(b2*384 + o1))*HW + (size_t)h*128;
                float* r2 = out + ((size_t)(b2*384 + o2))*HW + (size_t)h*128;
#pragma unroll
                for (int g = 0; g < 8; g++){
                    int w = nw*64 + g*8 + 2*(l & 3);
                    float2 v1, v2;
                    v1.x = fmaxf(fmaf(acc[f][g][0], sc1, sh1), 0.f);
                    v1.y = fmaxf(fmaf(acc[f][g][1], sc1, sh1), 0.f);
                    v2.x = fmaxf(fmaf(acc[f][g][2], sc2, sh2), 0.f);
                    v2.y = fmaxf(fmaf(acc[f][g][3], sc2, sh2), 0.f);
                    *(float2*)(r1 + w) = v1;
                    *(float2*)(r2 + w) = v2;
                }
            }
        }
    }
}

// =============================================================================
extern "C" void kernel_launch(void* const* d_in, const int* in_sizes, int n_in,
                              void* d_out, int out_size)
{
    const float* x  = (const float*)d_in[0];
    const float* xf = (const float*)d_in[1];
    const float* xr = (const float*)d_in[2];
    const float* Wx = (const float*)d_in[3];
    const float* bx = (const float*)d_in[4];
    const float* W1 = (const float*)d_in[5];
    const float* b1 = (const float*)d_in[6];
    const float* W2 = (const float*)d_in[7];
    const float* b2 = (const float*)d_in[8];
    const float* Wf = (const float*)d_in[9];
    const float* bf = (const float*)d_in[10];
    const float* Wr = (const float*)d_in[11];
    const float* br_ = (const float*)d_in[12];
    const float* Wm = (const float*)d_in[13];
    const float* bm = (const float*)d_in[14];
    const float* gamma = (const float*)d_in[15];
    const float* beta  = (const float*)d_in[16];
    const float* rmean = (const float*)d_in[17];
    const float* rvar  = (const float*)d_in[18];
    float* out = (float*)d_out;

    cudaFuncSetAttribute(xpose_cvt,   cudaFuncAttributeMaxDynamicSharedMemorySize, 68096);
    cudaFuncSetAttribute(wcompose_kernel, cudaFuncAttributeMaxDynamicSharedMemorySize, 65536);
    cudaFuncSetAttribute(front_mma,   cudaFuncAttributeMaxDynamicSharedMemorySize, FSMEM);
    cudaFuncSetAttribute(conv3x3_tc,  cudaFuncAttributeMaxDynamicSharedMemorySize, SMEM3);

    xpose_cvt<<<dim3(3, 128, 8), 256, 68096>>>(x, xf, xr);
    wcompose_kernel<<<5, 256, 65536>>>(Wx, bx, W1, b1, W2, b2, Wf, bf, Wr, br_);
    front_mma<<<dim3(128, 8), 256, FSMEM>>>();
    presplit_kernel<<<5184, 256>>>(Wm);
    conv3x3_tc<<<NCTA, 128, SMEM3>>>(bm, gamma, beta, rmean, rvar, out);
}